// round 5
// baseline (speedup 1.0000x reference)
#include <cuda_runtime.h>
#include <cuda_fp16.h>
#include <cuda_bf16.h>
#include <mma.h>
#include <math.h>
#include <stdint.h>

using namespace nvcuda;

// Problem constants
#define NNODE 50000
#define NEDGE 800000
#define FIN 128
#define COUT 128   // NH*FOUT
#define NH 4

#define SCAN_BLK 1024
#define NSCAN_BLKS ((NNODE + SCAN_BLK - 1) / SCAN_BLK)   // 49

#define TILE_M 128
#define NTILES ((NNODE + TILE_M - 1) / TILE_M)           // 391
#define LDA 136   // padded leading dim (bf16 elems) for smem tiles

// ---------------- device scratch (no allocations allowed) ----------------
__device__ __half g_src_proj_h[NNODE * COUT];      // 12.8 MB (fp16)
__device__ float4 g_scores_src[NNODE];
__device__ float4 g_scores_trg[NNODE];
__device__ int    g_count[NNODE];
__device__ int    g_offsets[NNODE + 1];
__device__ int    g_blocksum[NSCAN_BLKS];
__device__ int    g_blockcarry[NSCAN_BLKS];
__device__ int    g_edge_rank[NEDGE];
__device__ float4 g_edge_exp[NEDGE];               // 12.8 MB
__device__ int    g_sorted_si[NEDGE];
__device__ float4 g_sorted_exp[NEDGE];             // 12.8 MB
__device__ float  g_Vt[FIN * NH];

// ---------------- small kernels ----------------

__global__ void zero_kernel() {
    int i = blockIdx.x * blockDim.x + threadIdx.x;
    int stride = gridDim.x * blockDim.x;
    for (int k = i; k < NNODE; k += stride) g_count[k] = 0;
}

// Vt[f,h] = sum_j Wt[f, h*32+j] * a_trg[h, j]
__global__ void fold_kernel(const float* __restrict__ Wt,
                            const float* __restrict__ a_trg) {
    int f = threadIdx.x;
    #pragma unroll
    for (int h = 0; h < NH; h++) {
        float s = 0.0f;
        #pragma unroll
        for (int j = 0; j < 32; j++)
            s += Wt[f * COUT + h * 32 + j] * a_trg[h * 32 + j];
        g_Vt[f * NH + h] = s;
    }
}

// scores_trg = trg @ Vt   (warp per node)
__global__ void strg_kernel(const float* __restrict__ trg) {
    __shared__ float Vsh[FIN * NH];
    for (int i = threadIdx.x; i < FIN * NH; i += blockDim.x) Vsh[i] = g_Vt[i];
    __syncthreads();

    int gwarp = (blockIdx.x * blockDim.x + threadIdx.x) >> 5;
    int lane = threadIdx.x & 31;
    if (gwarp >= NNODE) return;

    float4 xv = ((const float4*)(trg + (size_t)gwarp * FIN))[lane];
    int f0 = lane * 4;
    float a0, a1, a2, a3;
    a0 = xv.x * Vsh[(f0+0)*4+0] + xv.y * Vsh[(f0+1)*4+0] + xv.z * Vsh[(f0+2)*4+0] + xv.w * Vsh[(f0+3)*4+0];
    a1 = xv.x * Vsh[(f0+0)*4+1] + xv.y * Vsh[(f0+1)*4+1] + xv.z * Vsh[(f0+2)*4+1] + xv.w * Vsh[(f0+3)*4+1];
    a2 = xv.x * Vsh[(f0+0)*4+2] + xv.y * Vsh[(f0+1)*4+2] + xv.z * Vsh[(f0+2)*4+2] + xv.w * Vsh[(f0+3)*4+2];
    a3 = xv.x * Vsh[(f0+0)*4+3] + xv.y * Vsh[(f0+1)*4+3] + xv.z * Vsh[(f0+2)*4+3] + xv.w * Vsh[(f0+3)*4+3];
    #pragma unroll
    for (int o = 16; o > 0; o >>= 1) {
        a0 += __shfl_xor_sync(0xffffffffu, a0, o);
        a1 += __shfl_xor_sync(0xffffffffu, a1, o);
        a2 += __shfl_xor_sync(0xffffffffu, a2, o);
        a3 += __shfl_xor_sync(0xffffffffu, a3, o);
    }
    if (lane == 0) g_scores_trg[gwarp] = make_float4(a0, a1, a2, a3);
}

// ---------------- WMMA bf16 split projection GEMM ----------------
// D[128x128] = A_tile(src, split bf16) @ B(Ws, split bf16), fp32 accum.
// Terms: Ahi*Bhi + Ahi*Blo + Alo*Bhi.
// smem layout (bytes):
//   sAhi @ 0,       128*LDA*2 = 34816
//   sAlo @ 34816
//   sBhi @ 69632
//   sBlo @ 104448
//   ash  @ 139264 (128 floats)
// epilogue overlays [0, 65536): warp w uses [w*8192, (w+1)*8192) as 16x128 f32.
#define SM_AHI 0
#define SM_ALO 34816
#define SM_BHI 69632
#define SM_BLO 104448
#define SM_ASH 139264
#define SM_TOT (SM_ASH + 512)

__device__ __forceinline__ void split_store(char* base, int elem_off,
                                            float4 v) {
    __nv_bfloat16 h0 = __float2bfloat16(v.x);
    __nv_bfloat16 h1 = __float2bfloat16(v.y);
    __nv_bfloat16 h2 = __float2bfloat16(v.z);
    __nv_bfloat16 h3 = __float2bfloat16(v.w);
    __nv_bfloat16 l0 = __float2bfloat16(v.x - __bfloat162float(h0));
    __nv_bfloat16 l1 = __float2bfloat16(v.y - __bfloat162float(h1));
    __nv_bfloat16 l2 = __float2bfloat16(v.z - __bfloat162float(h2));
    __nv_bfloat16 l3 = __float2bfloat16(v.w - __bfloat162float(h3));
    __nv_bfloat162 hA = __halves2bfloat162(h0, h1);
    __nv_bfloat162 hB = __halves2bfloat162(h2, h3);
    __nv_bfloat162 lA = __halves2bfloat162(l0, l1);
    __nv_bfloat162 lB = __halves2bfloat162(l2, l3);
    uint2 wh, wl;
    wh.x = *(uint32_t*)&hA; wh.y = *(uint32_t*)&hB;
    wl.x = *(uint32_t*)&lA; wl.y = *(uint32_t*)&lB;
    *(uint2*)(base + SM_AHI + (size_t)elem_off * 2) = wh;   // hi image
    *(uint2*)(base + SM_ALO - SM_AHI + SM_AHI + (size_t)elem_off * 2 + (SM_ALO - SM_AHI) - (SM_ALO - SM_AHI)) = wl; // placeholder (unused)
}

__global__ void __launch_bounds__(256, 1)
proj_wmma_kernel(const float* __restrict__ src,
                 const float* __restrict__ Ws,
                 const float* __restrict__ a_src) {
    extern __shared__ char smem[];
    int tid = threadIdx.x;
    int w = tid >> 5;
    int lane = tid & 31;

    int n0 = blockIdx.x * TILE_M;

    __nv_bfloat16* sAhi = (__nv_bfloat16*)(smem + SM_AHI);
    __nv_bfloat16* sAlo = (__nv_bfloat16*)(smem + SM_ALO);
    __nv_bfloat16* sBhi = (__nv_bfloat16*)(smem + SM_BHI);
    __nv_bfloat16* sBlo = (__nv_bfloat16*)(smem + SM_BLO);
    float* ash = (float*)(smem + SM_ASH);

    // load + split A tile (zero-pad rows beyond NNODE)
    {
        const float4* s4 = (const float4*)src;
        for (int idx = tid; idx < TILE_M * 32; idx += 256) {
            int r = idx >> 5, c4 = idx & 31;
            float4 v = make_float4(0.f, 0.f, 0.f, 0.f);
            int n = n0 + r;
            if (n < NNODE) v = s4[(size_t)n * 32 + c4];
            __nv_bfloat16 h0 = __float2bfloat16(v.x);
            __nv_bfloat16 h1 = __float2bfloat16(v.y);
            __nv_bfloat16 h2 = __float2bfloat16(v.z);
            __nv_bfloat16 h3 = __float2bfloat16(v.w);
            __nv_bfloat16 l0 = __float2bfloat16(v.x - __bfloat162float(h0));
            __nv_bfloat16 l1 = __float2bfloat16(v.y - __bfloat162float(h1));
            __nv_bfloat16 l2 = __float2bfloat16(v.z - __bfloat162float(h2));
            __nv_bfloat16 l3 = __float2bfloat16(v.w - __bfloat162float(h3));
            __nv_bfloat162 hA = __halves2bfloat162(h0, h1);
            __nv_bfloat162 hB = __halves2bfloat162(h2, h3);
            __nv_bfloat162 lA = __halves2bfloat162(l0, l1);
            __nv_bfloat162 lB = __halves2bfloat162(l2, l3);
            int eo = r * LDA + c4 * 4;
            uint2 wh, wl;
            wh.x = *(uint32_t*)&hA; wh.y = *(uint32_t*)&hB;
            wl.x = *(uint32_t*)&lA; wl.y = *(uint32_t*)&lB;
            *(uint2*)(sAhi + eo) = wh;
            *(uint2*)(sAlo + eo) = wl;
        }
        // load + split B = Ws (K=FIN rows, N=COUT cols, row-major)
        const float4* w4 = (const float4*)Ws;
        for (int idx = tid; idx < FIN * 32; idx += 256) {
            int f = idx >> 5, c4 = idx & 31;
            float4 v = w4[(size_t)f * 32 + c4];
            __nv_bfloat16 h0 = __float2bfloat16(v.x);
            __nv_bfloat16 h1 = __float2bfloat16(v.y);
            __nv_bfloat16 h2 = __float2bfloat16(v.z);
            __nv_bfloat16 h3 = __float2bfloat16(v.w);
            __nv_bfloat16 l0 = __float2bfloat16(v.x - __bfloat162float(h0));
            __nv_bfloat16 l1 = __float2bfloat16(v.y - __bfloat162float(h1));
            __nv_bfloat16 l2 = __float2bfloat16(v.z - __bfloat162float(h2));
            __nv_bfloat16 l3 = __float2bfloat16(v.w - __bfloat162float(h3));
            __nv_bfloat162 hA = __halves2bfloat162(h0, h1);
            __nv_bfloat162 hB = __halves2bfloat162(h2, h3);
            __nv_bfloat162 lA = __halves2bfloat162(l0, l1);
            __nv_bfloat162 lB = __halves2bfloat162(l2, l3);
            int eo = f * LDA + c4 * 4;
            uint2 wh, wl;
            wh.x = *(uint32_t*)&hA; wh.y = *(uint32_t*)&hB;
            wl.x = *(uint32_t*)&lA; wl.y = *(uint32_t*)&lB;
            *(uint2*)(sBhi + eo) = wh;
            *(uint2*)(sBlo + eo) = wl;
        }
        for (int i = tid; i < COUT; i += 256) ash[i] = a_src[i];
    }
    __syncthreads();

    // MMA: warp w owns rows 16w..16w+15, 8 column tiles
    wmma::fragment<wmma::accumulator, 16, 16, 16, float> acc[8];
    #pragma unroll
    for (int n = 0; n < 8; n++) wmma::fill_fragment(acc[n], 0.0f);

    #pragma unroll
    for (int k = 0; k < 8; k++) {
        wmma::fragment<wmma::matrix_a, 16, 16, 16, __nv_bfloat16, wmma::row_major> a_hi, a_lo;
        wmma::load_matrix_sync(a_hi, sAhi + w * 16 * LDA + k * 16, LDA);
        wmma::load_matrix_sync(a_lo, sAlo + w * 16 * LDA + k * 16, LDA);
        #pragma unroll
        for (int n = 0; n < 8; n++) {
            wmma::fragment<wmma::matrix_b, 16, 16, 16, __nv_bfloat16, wmma::row_major> b_hi, b_lo;
            wmma::load_matrix_sync(b_hi, sBhi + k * 16 * LDA + n * 16, LDA);
            wmma::load_matrix_sync(b_lo, sBlo + k * 16 * LDA + n * 16, LDA);
            wmma::mma_sync(acc[n], a_hi, b_hi, acc[n]);
            wmma::mma_sync(acc[n], a_hi, b_lo, acc[n]);
            wmma::mma_sync(acc[n], a_lo, b_hi, acc[n]);
        }
    }

    // epilogue: overlay warp-private 16x128 f32 strips onto A smem region
    __syncthreads();
    float* epi = (float*)(smem + w * 8192);
    #pragma unroll
    for (int n = 0; n < 8; n++)
        wmma::store_matrix_sync(epi + n * 16, acc[n], 128, wmma::mem_row_major);
    __syncwarp();

    {
        int row = lane >> 1;          // 0..15
        int half = lane & 1;          // 0/1: cols 64*half..+63
        int m = n0 + w * 16 + row;
        if (m < NNODE) {
            const float* v = epi + row * 128 + half * 64;
            // scores for heads 2*half, 2*half+1
            float p0 = 0.f, p1 = 0.f;
            #pragma unroll
            for (int j = 0; j < 32; j++) {
                p0 += v[j]      * ash[half * 64 + j];
                p1 += v[32 + j] * ash[half * 64 + 32 + j];
            }
            ((float2*)&g_scores_src[m])[half] = make_float2(p0, p1);

            // fp16 store of 64 cols (128 B contiguous)
            uint32_t pk[16];
            #pragma unroll
            for (int j = 0; j < 16; j++) {
                __half2 h = __floats2half2_rn(v[2*j], v[2*j+1]);
                pk[j] = *(uint32_t*)&h;
            }
            uint32_t pk2[16];
            #pragma unroll
            for (int j = 0; j < 16; j++) {
                __half2 h = __floats2half2_rn(v[32 + 2*j], v[32 + 2*j+1]);
                pk2[j] = *(uint32_t*)&h;
            }
            uint4* dst = (uint4*)(g_src_proj_h + (size_t)m * COUT + half * 64);
            #pragma unroll
            for (int q = 0; q < 4; q++)
                dst[q] = make_uint4(pk[q*4], pk[q*4+1], pk[q*4+2], pk[q*4+3]);
            #pragma unroll
            for (int q = 0; q < 4; q++)
                dst[4 + q] = make_uint4(pk2[q*4], pk2[q*4+1], pk2[q*4+2], pk2[q*4+3]);
        }
    }
}

// ---------------- edge pipeline ----------------

__device__ __forceinline__ float lrelu_exp(float s) {
    float l = s > 0.0f ? s : 0.2f * s;
    return __expf(l);
}

__global__ void edge1_kernel(const int* __restrict__ ei) {
    int e = blockIdx.x * blockDim.x + threadIdx.x;
    if (e >= NEDGE) return;
    int si = ei[e];
    int ti = ei[NEDGE + e];
    float4 ss = g_scores_src[si];
    float4 st = g_scores_trg[ti];
    float4 ex;
    ex.x = lrelu_exp(ss.x + st.x);
    ex.y = lrelu_exp(ss.y + st.y);
    ex.z = lrelu_exp(ss.z + st.z);
    ex.w = lrelu_exp(ss.w + st.w);
    g_edge_exp[e] = ex;
    g_edge_rank[e] = atomicAdd(&g_count[ti], 1);
}

__global__ void scanA_kernel() {
    __shared__ int sh[SCAN_BLK];
    int tid = threadIdx.x;
    int gi = blockIdx.x * SCAN_BLK + tid;
    int v = (gi < NNODE) ? g_count[gi] : 0;
    sh[tid] = v;
    __syncthreads();
    #pragma unroll
    for (int off = 1; off < SCAN_BLK; off <<= 1) {
        int t = (tid >= off) ? sh[tid - off] : 0;
        __syncthreads();
        sh[tid] += t;
        __syncthreads();
    }
    if (gi < NNODE) g_offsets[gi + 1] = sh[tid];
    if (tid == SCAN_BLK - 1) g_blocksum[blockIdx.x] = sh[tid];
}

__global__ void scanB_kernel() {
    if (threadIdx.x == 0) {
        int c = 0;
        for (int b = 0; b < NSCAN_BLKS; b++) {
            g_blockcarry[b] = c;
            c += g_blocksum[b];
        }
        g_offsets[0] = 0;
    }
}

__global__ void scanC_kernel() {
    int tid = threadIdx.x;
    int gi = blockIdx.x * SCAN_BLK + tid;
    if (blockIdx.x == 0) return;
    if (gi < NNODE) g_offsets[gi + 1] += g_blockcarry[blockIdx.x];
}

__global__ void edge2_kernel(const int* __restrict__ ei) {
    int e = blockIdx.x * blockDim.x + threadIdx.x;
    if (e >= NEDGE) return;
    int si = ei[e];
    int ti = ei[NEDGE + e];
    int pos = g_offsets[ti] + g_edge_rank[e];
    g_sorted_si[pos] = si;
    g_sorted_exp[pos] = g_edge_exp[e];
}

// aggregation: warp per target; fp16 gather, 4-deep load-first pipeline.
__global__ void agg_kernel(float* __restrict__ out) {
    int gwarp = (blockIdx.x * blockDim.x + threadIdx.x) >> 5;
    int lane = threadIdx.x & 31;
    if (gwarp >= NNODE) return;

    int s = g_offsets[gwarp];
    int e2 = g_offsets[gwarp + 1];

    const __half2* hsp = (const __half2*)g_src_proj_h;
    bool lowHalf = (lane < 16);

    float2 accA = make_float2(0.f, 0.f);
    float2 accB = make_float2(0.f, 0.f);
    float d0 = 0.f, d1 = 0.f, d2 = 0.f, d3 = 0.f;

    int i = s;
    for (; i + 4 <= e2; i += 4) {
        int si0 = g_sorted_si[i+0];
        int si1 = g_sorted_si[i+1];
        int si2 = g_sorted_si[i+2];
        int si3 = g_sorted_si[i+3];
        float4 ex0 = g_sorted_exp[i+0];
        float4 ex1 = g_sorted_exp[i+1];
        float4 ex2 = g_sorted_exp[i+2];
        float4 ex3 = g_sorted_exp[i+3];
        __half2 vA0 = hsp[(size_t)si0*64 + lane];
        __half2 vB0 = hsp[(size_t)si0*64 + 32 + lane];
        __half2 vA1 = hsp[(size_t)si1*64 + lane];
        __half2 vB1 = hsp[(size_t)si1*64 + 32 + lane];
        __half2 vA2 = hsp[(size_t)si2*64 + lane];
        __half2 vB2 = hsp[(size_t)si2*64 + 32 + lane];
        __half2 vA3 = hsp[(size_t)si3*64 + lane];
        __half2 vB3 = hsp[(size_t)si3*64 + 32 + lane];

        float wA0 = lowHalf ? ex0.x : ex0.y, wB0 = lowHalf ? ex0.z : ex0.w;
        float wA1 = lowHalf ? ex1.x : ex1.y, wB1 = lowHalf ? ex1.z : ex1.w;
        float wA2 = lowHalf ? ex2.x : ex2.y, wB2 = lowHalf ? ex2.z : ex2.w;
        float wA3 = lowHalf ? ex3.x : ex3.y, wB3 = lowHalf ? ex3.z : ex3.w;

        float2 f;
        f = __half22float2(vA0); accA.x += wA0*f.x; accA.y += wA0*f.y;
        f = __half22float2(vB0); accB.x += wB0*f.x; accB.y += wB0*f.y;
        f = __half22float2(vA1); accA.x += wA1*f.x; accA.y += wA1*f.y;
        f = __half22float2(vB1); accB.x += wB1*f.x; accB.y += wB1*f.y;
        f = __half22float2(vA2); accA.x += wA2*f.x; accA.y += wA2*f.y;
        f = __half22float2(vB2); accB.x += wB2*f.x; accB.y += wB2*f.y;
        f = __half22float2(vA3); accA.x += wA3*f.x; accA.y += wA3*f.y;
        f = __half22float2(vB3); accB.x += wB3*f.x; accB.y += wB3*f.y;

        d0 += ex0.x + ex1.x + ex2.x + ex3.x;
        d1 += ex0.y + ex1.y + ex2.y + ex3.y;
        d2 += ex0.z + ex1.z + ex2.z + ex3.z;
        d3 += ex0.w + ex1.w + ex2.w + ex3.w;
    }
    for (; i < e2; i++) {
        int si = g_sorted_si[i];
        float4 ex = g_sorted_exp[i];
        __half2 vA = hsp[(size_t)si*64 + lane];
        __half2 vB = hsp[(size_t)si*64 + 32 + lane];
        float wA = lowHalf ? ex.x : ex.y;
        float wB = lowHalf ? ex.z : ex.w;
        float2 f;
        f = __half22float2(vA); accA.x += wA*f.x; accA.y += wA*f.y;
        f = __half22float2(vB); accB.x += wB*f.x; accB.y += wB*f.y;
        d0 += ex.x; d1 += ex.y; d2 += ex.z; d3 += ex.w;
    }

    float r0 = 1.0f / (d0 + 1e-16f);
    float r1 = 1.0f / (d1 + 1e-16f);
    float r2 = 1.0f / (d2 + 1e-16f);
    float r3 = 1.0f / (d3 + 1e-16f);

    float rA = lowHalf ? r0 : r1;
    float rB = lowHalf ? r2 : r3;

    float2* o = (float2*)(out + (size_t)gwarp * COUT);
    o[lane]      = make_float2(accA.x * rA, accA.y * rA);
    o[32 + lane] = make_float2(accB.x * rB, accB.y * rB);
}

// ---------------- launch ----------------

extern "C" void kernel_launch(void* const* d_in, const int* in_sizes, int n_in,
                              void* d_out, int out_size) {
    const float* trg   = (const float*)d_in[0];
    const float* src   = (const float*)d_in[1];
    const int*   ei    = (const int*)d_in[2];
    const float* Wt    = (const float*)d_in[3];
    const float* Ws    = (const float*)d_in[4];
    const float* a_src = (const float*)d_in[5];
    const float* a_trg = (const float*)d_in[6];
    float* out = (float*)d_out;

    cudaFuncSetAttribute(proj_wmma_kernel,
                         cudaFuncAttributeMaxDynamicSharedMemorySize, SM_TOT);

    zero_kernel<<<64, 256>>>();
    fold_kernel<<<1, 128>>>(Wt, a_trg);

    {
        int blocks = (NNODE * 32 + 255) / 256;
        strg_kernel<<<blocks, 256>>>(trg);
    }

    proj_wmma_kernel<<<NTILES, 256, SM_TOT>>>(src, Ws, a_src);

    {
        int blocks = (NEDGE + 255) / 256;
        edge1_kernel<<<blocks, 256>>>(ei);
    }

    scanA_kernel<<<NSCAN_BLKS, SCAN_BLK>>>();
    scanB_kernel<<<1, 32>>>();
    scanC_kernel<<<NSCAN_BLKS, SCAN_BLK>>>();

    {
        int blocks = (NEDGE + 255) / 256;
        edge2_kernel<<<blocks, 256>>>(ei);
    }

    {
        int blocks = (NNODE * 32 + 255) / 256;
        agg_kernel<<<blocks, 256>>>(out);
    }
}

// round 6
// speedup vs baseline: 1.1700x; 1.1700x over previous
#include <cuda_runtime.h>
#include <cuda_fp16.h>
#include <math.h>

// Problem constants
#define NNODE 50000
#define NEDGE 800000
#define FIN 128
#define COUT 128   // NH*FOUT
#define NH 4

#define PROJ_WARPS 8
#define NPW 8            // nodes per warp per iteration
#define SCAN_BLK 1024
#define NSCAN_BLKS ((NNODE + SCAN_BLK - 1) / SCAN_BLK)   // 49

// ---------------- device scratch (no allocations allowed) ----------------
__device__ __half g_src_proj_h[NNODE * COUT];      // 12.8 MB (fp16)
__device__ float4 g_scores_src[NNODE];
__device__ float4 g_scores_trg[NNODE];
__device__ int    g_count[NNODE];
__device__ int    g_offsets[NNODE + 1];
__device__ int    g_blocksum[NSCAN_BLKS];
__device__ int    g_blockcarry[NSCAN_BLKS];
__device__ int    g_edge_rank[NEDGE];
__device__ int    g_sorted_si[NEDGE];
__device__ float  g_Vt[FIN * NH];

// ---------------- kernels ----------------

__global__ void zero_kernel() {
    int i = blockIdx.x * blockDim.x + threadIdx.x;
    int stride = gridDim.x * blockDim.x;
    for (int k = i; k < NNODE; k += stride) g_count[k] = 0;
}

// Vt[f,h] = sum_j Wt[f, h*32+j] * a_trg[h, j]
__global__ void fold_kernel(const float* __restrict__ Wt,
                            const float* __restrict__ a_trg) {
    int f = threadIdx.x;
    #pragma unroll
    for (int h = 0; h < NH; h++) {
        float s = 0.0f;
        #pragma unroll
        for (int j = 0; j < 32; j++)
            s += Wt[f * COUT + h * 32 + j] * a_trg[h * 32 + j];
        g_Vt[f * NH + h] = s;
    }
}

// scores_trg = trg @ Vt   (warp per node)
__global__ void strg_kernel(const float* __restrict__ trg) {
    __shared__ float Vsh[FIN * NH];
    for (int i = threadIdx.x; i < FIN * NH; i += blockDim.x) Vsh[i] = g_Vt[i];
    __syncthreads();

    int gwarp = (blockIdx.x * blockDim.x + threadIdx.x) >> 5;
    int lane = threadIdx.x & 31;
    if (gwarp >= NNODE) return;

    float4 xv = ((const float4*)(trg + (size_t)gwarp * FIN))[lane];
    int f0 = lane * 4;
    float a0, a1, a2, a3;
    a0 = xv.x * Vsh[(f0+0)*4+0] + xv.y * Vsh[(f0+1)*4+0] + xv.z * Vsh[(f0+2)*4+0] + xv.w * Vsh[(f0+3)*4+0];
    a1 = xv.x * Vsh[(f0+0)*4+1] + xv.y * Vsh[(f0+1)*4+1] + xv.z * Vsh[(f0+2)*4+1] + xv.w * Vsh[(f0+3)*4+1];
    a2 = xv.x * Vsh[(f0+0)*4+2] + xv.y * Vsh[(f0+1)*4+2] + xv.z * Vsh[(f0+2)*4+2] + xv.w * Vsh[(f0+3)*4+2];
    a3 = xv.x * Vsh[(f0+0)*4+3] + xv.y * Vsh[(f0+1)*4+3] + xv.z * Vsh[(f0+2)*4+3] + xv.w * Vsh[(f0+3)*4+3];
    #pragma unroll
    for (int o = 16; o > 0; o >>= 1) {
        a0 += __shfl_xor_sync(0xffffffffu, a0, o);
        a1 += __shfl_xor_sync(0xffffffffu, a1, o);
        a2 += __shfl_xor_sync(0xffffffffu, a2, o);
        a3 += __shfl_xor_sync(0xffffffffu, a3, o);
    }
    if (lane == 0) g_scores_trg[gwarp] = make_float4(a0, a1, a2, a3);
}

// src_proj = src @ Ws (register-blocked), fused scores_src epilogue.
// Output stored fp16 (consumed only by agg gather).
__global__ void proj_kernel(const float* __restrict__ src,
                            const float* __restrict__ Ws,
                            const float* __restrict__ a_src) {
    extern __shared__ float sh[];
    float* Wsh = sh;                        // 128*128
    float* ash = Wsh + FIN * COUT;          // 128
    float* xsh = ash + COUT;                // PROJ_WARPS * NPW * FIN

    {
        const float4* w4 = (const float4*)Ws;
        float4* s4 = (float4*)Wsh;
        for (int i = threadIdx.x; i < FIN * COUT / 4; i += blockDim.x) s4[i] = w4[i];
        for (int i = threadIdx.x; i < COUT; i += blockDim.x) ash[i] = a_src[i];
    }
    __syncthreads();

    int lane = threadIdx.x & 31;
    int w = threadIdx.x >> 5;
    float* myx = xsh + w * (NPW * FIN);

    const int ngroups = NNODE / NPW;         // 6250 (exact)
    int group = blockIdx.x * PROJ_WARPS + w;
    int gstride = gridDim.x * PROJ_WARPS;

    for (int g = group; g < ngroups; g += gstride) {
        int n0 = g * NPW;
        #pragma unroll
        for (int r = 0; r < NPW; r++) {
            float4 xv = ((const float4*)(src + (size_t)(n0 + r) * FIN))[lane];
            ((float4*)(myx + r * FIN))[lane] = xv;
        }
        __syncwarp();

        float acc[NPW][4];
        #pragma unroll
        for (int r = 0; r < NPW; r++) { acc[r][0]=0.f; acc[r][1]=0.f; acc[r][2]=0.f; acc[r][3]=0.f; }

        #pragma unroll 4
        for (int f = 0; f < FIN; f++) {
            float4 wv = ((const float4*)(Wsh + f * COUT))[lane];
            #pragma unroll
            for (int r = 0; r < NPW; r++) {
                float xf = myx[r * FIN + f];
                acc[r][0] += xf * wv.x;
                acc[r][1] += xf * wv.y;
                acc[r][2] += xf * wv.z;
                acc[r][3] += xf * wv.w;
            }
        }

        int h = lane >> 3;
        int fi = (lane & 7) * 4;
        float c0 = ash[h * 32 + fi + 0];
        float c1 = ash[h * 32 + fi + 1];
        float c2 = ash[h * 32 + fi + 2];
        float c3 = ash[h * 32 + fi + 3];

        #pragma unroll
        for (int r = 0; r < NPW; r++) {
            int n = n0 + r;
            __half2 lo = __floats2half2_rn(acc[r][0], acc[r][1]);
            __half2 hi = __floats2half2_rn(acc[r][2], acc[r][3]);
            uint2 pk;
            pk.x = *(unsigned int*)&lo;
            pk.y = *(unsigned int*)&hi;
            ((uint2*)(g_src_proj_h + (size_t)n * COUT))[lane] = pk;

            float p = acc[r][0]*c0 + acc[r][1]*c1 + acc[r][2]*c2 + acc[r][3]*c3;
            p += __shfl_xor_sync(0xffffffffu, p, 4);
            p += __shfl_xor_sync(0xffffffffu, p, 2);
            p += __shfl_xor_sync(0xffffffffu, p, 1);
            if ((lane & 7) == 0) ((float*)g_scores_src)[n * 4 + h] = p;
        }
        __syncwarp();
    }
}

// pass 1: degree counts + ranks only (reads targets only)
__global__ void edge1_kernel(const int* __restrict__ ei) {
    int e = blockIdx.x * blockDim.x + threadIdx.x;
    if (e >= NEDGE) return;
    int ti = ei[NEDGE + e];
    g_edge_rank[e] = atomicAdd(&g_count[ti], 1);
}

// two-level scan
__global__ void scanA_kernel() {
    __shared__ int sh[SCAN_BLK];
    int tid = threadIdx.x;
    int gi = blockIdx.x * SCAN_BLK + tid;
    int v = (gi < NNODE) ? g_count[gi] : 0;
    sh[tid] = v;
    __syncthreads();
    #pragma unroll
    for (int off = 1; off < SCAN_BLK; off <<= 1) {
        int t = (tid >= off) ? sh[tid - off] : 0;
        __syncthreads();
        sh[tid] += t;
        __syncthreads();
    }
    if (gi < NNODE) g_offsets[gi + 1] = sh[tid];
    if (tid == SCAN_BLK - 1) g_blocksum[blockIdx.x] = sh[tid];
}

__global__ void scanB_kernel() {
    if (threadIdx.x == 0) {
        int c = 0;
        for (int b = 0; b < NSCAN_BLKS; b++) {
            g_blockcarry[b] = c;
            c += g_blocksum[b];
        }
        g_offsets[0] = 0;
    }
}

__global__ void scanC_kernel() {
    int tid = threadIdx.x;
    int gi = blockIdx.x * SCAN_BLK + tid;
    if (blockIdx.x == 0) return;
    if (gi < NNODE) g_offsets[gi + 1] += g_blockcarry[blockIdx.x];
}

// pass 2: permute source ids into CSR order (4 B payload per edge)
__global__ void edge2_kernel(const int* __restrict__ ei) {
    int e = blockIdx.x * blockDim.x + threadIdx.x;
    if (e >= NEDGE) return;
    int si = ei[e];
    int ti = ei[NEDGE + e];
    int pos = g_offsets[ti] + g_edge_rank[e];
    g_sorted_si[pos] = si;
}

// aggregation: warp per target node. Recomputes exp from scores (L2-hot
// broadcast reads), gathers fp16 src_proj rows, denominator per-lane free.
// Lane layout: load1 -> cols 2l,2l+1 (head l<16?0:1), load2 -> cols 64+2l (head l<16?2:3)
__global__ void agg_kernel(float* __restrict__ out) {
    int gwarp = (blockIdx.x * blockDim.x + threadIdx.x) >> 5;
    int lane = threadIdx.x & 31;
    if (gwarp >= NNODE) return;

    int s = g_offsets[gwarp];
    int e2 = g_offsets[gwarp + 1];

    const __half2* hsp = (const __half2*)g_src_proj_h;
    bool lowHalf = (lane < 16);

    float4 st = g_scores_trg[gwarp];
    float stA = lowHalf ? st.x : st.y;       // this lane's head for block A
    float stB = lowHalf ? st.z : st.w;       // this lane's head for block B

    float2 accA = make_float2(0.f, 0.f);
    float2 accB = make_float2(0.f, 0.f);
    float dA = 0.f, dB = 0.f;

    int i = s;
    for (; i + 4 <= e2; i += 4) {
        int si0 = g_sorted_si[i+0];
        int si1 = g_sorted_si[i+1];
        int si2 = g_sorted_si[i+2];
        int si3 = g_sorted_si[i+3];
        float4 ss0 = g_scores_src[si0];
        float4 ss1 = g_scores_src[si1];
        float4 ss2 = g_scores_src[si2];
        float4 ss3 = g_scores_src[si3];
        __half2 vA0 = hsp[(size_t)si0*64 + lane];
        __half2 vB0 = hsp[(size_t)si0*64 + 32 + lane];
        __half2 vA1 = hsp[(size_t)si1*64 + lane];
        __half2 vB1 = hsp[(size_t)si1*64 + 32 + lane];
        __half2 vA2 = hsp[(size_t)si2*64 + lane];
        __half2 vB2 = hsp[(size_t)si2*64 + 32 + lane];
        __half2 vA3 = hsp[(size_t)si3*64 + lane];
        __half2 vB3 = hsp[(size_t)si3*64 + 32 + lane];

        float sA0 = (lowHalf ? ss0.x : ss0.y) + stA;
        float sB0 = (lowHalf ? ss0.z : ss0.w) + stB;
        float sA1 = (lowHalf ? ss1.x : ss1.y) + stA;
        float sB1 = (lowHalf ? ss1.z : ss1.w) + stB;
        float sA2 = (lowHalf ? ss2.x : ss2.y) + stA;
        float sB2 = (lowHalf ? ss2.z : ss2.w) + stB;
        float sA3 = (lowHalf ? ss3.x : ss3.y) + stA;
        float sB3 = (lowHalf ? ss3.z : ss3.w) + stB;
        float wA0 = __expf(fmaxf(sA0, 0.2f * sA0));
        float wB0 = __expf(fmaxf(sB0, 0.2f * sB0));
        float wA1 = __expf(fmaxf(sA1, 0.2f * sA1));
        float wB1 = __expf(fmaxf(sB1, 0.2f * sB1));
        float wA2 = __expf(fmaxf(sA2, 0.2f * sA2));
        float wB2 = __expf(fmaxf(sB2, 0.2f * sB2));
        float wA3 = __expf(fmaxf(sA3, 0.2f * sA3));
        float wB3 = __expf(fmaxf(sB3, 0.2f * sB3));

        float2 f;
        f = __half22float2(vA0); accA.x += wA0*f.x; accA.y += wA0*f.y;
        f = __half22float2(vB0); accB.x += wB0*f.x; accB.y += wB0*f.y;
        f = __half22float2(vA1); accA.x += wA1*f.x; accA.y += wA1*f.y;
        f = __half22float2(vB1); accB.x += wB1*f.x; accB.y += wB1*f.y;
        f = __half22float2(vA2); accA.x += wA2*f.x; accA.y += wA2*f.y;
        f = __half22float2(vB2); accB.x += wB2*f.x; accB.y += wB2*f.y;
        f = __half22float2(vA3); accA.x += wA3*f.x; accA.y += wA3*f.y;
        f = __half22float2(vB3); accB.x += wB3*f.x; accB.y += wB3*f.y;

        dA += wA0 + wA1 + wA2 + wA3;
        dB += wB0 + wB1 + wB2 + wB3;
    }
    for (; i < e2; i++) {
        int si = g_sorted_si[i];
        float4 ss = g_scores_src[si];
        __half2 vA = hsp[(size_t)si*64 + lane];
        __half2 vB = hsp[(size_t)si*64 + 32 + lane];
        float sA = (lowHalf ? ss.x : ss.y) + stA;
        float sB = (lowHalf ? ss.z : ss.w) + stB;
        float wA = __expf(fmaxf(sA, 0.2f * sA));
        float wB = __expf(fmaxf(sB, 0.2f * sB));
        float2 f;
        f = __half22float2(vA); accA.x += wA*f.x; accA.y += wA*f.y;
        f = __half22float2(vB); accB.x += wB*f.x; accB.y += wB*f.y;
        dA += wA; dB += wB;
    }

    float rA = 1.0f / (dA + 1e-16f);
    float rB = 1.0f / (dB + 1e-16f);

    float2* o = (float2*)(out + (size_t)gwarp * COUT);
    o[lane]      = make_float2(accA.x * rA, accA.y * rA);
    o[32 + lane] = make_float2(accB.x * rB, accB.y * rB);
}

// ---------------- launch ----------------

extern "C" void kernel_launch(void* const* d_in, const int* in_sizes, int n_in,
                              void* d_out, int out_size) {
    const float* trg   = (const float*)d_in[0];
    const float* src   = (const float*)d_in[1];
    const int*   ei    = (const int*)d_in[2];
    const float* Wt    = (const float*)d_in[3];
    const float* Ws    = (const float*)d_in[4];
    const float* a_src = (const float*)d_in[5];
    const float* a_trg = (const float*)d_in[6];
    float* out = (float*)d_out;

    const int PROJ_BLOCK = PROJ_WARPS * 32;  // 256
    size_t proj_smem = (size_t)(FIN * COUT + COUT + PROJ_WARPS * NPW * FIN) * sizeof(float);
    cudaFuncSetAttribute(proj_kernel, cudaFuncAttributeMaxDynamicSharedMemorySize,
                         (int)proj_smem);

    zero_kernel<<<64, 256>>>();
    fold_kernel<<<1, 128>>>(Wt, a_trg);

    {
        int blocks = (NNODE * 32 + 255) / 256;
        strg_kernel<<<blocks, 256>>>(trg);
    }

    proj_kernel<<<296, PROJ_BLOCK, proj_smem>>>(src, Ws, a_src);

    {
        int blocks = (NEDGE + 255) / 256;
        edge1_kernel<<<blocks, 256>>>(ei);
    }

    scanA_kernel<<<NSCAN_BLKS, SCAN_BLK>>>();
    scanB_kernel<<<1, 32>>>();
    scanC_kernel<<<NSCAN_BLKS, SCAN_BLK>>>();

    {
        int blocks = (NEDGE + 255) / 256;
        edge2_kernel<<<blocks, 256>>>(ei);
    }

    {
        int blocks = (NNODE * 32 + 255) / 256;
        agg_kernel<<<blocks, 256>>>(out);
    }
}

// round 7
// speedup vs baseline: 1.2568x; 1.0742x over previous
#include <cuda_runtime.h>
#include <cuda_fp16.h>
#include <math.h>

// Problem constants
#define NNODE 50000
#define NEDGE 800000
#define FIN 128
#define COUT 128   // NH*FOUT
#define NH 4

#define PROJ_WARPS 8
#define NPW 8            // nodes per warp per iteration
#define SCAN_BLK 1024
#define NSCAN_BLKS ((NNODE + SCAN_BLK - 1) / SCAN_BLK)   // 49

// ---------------- device scratch (no allocations allowed) ----------------
__device__ __half g_src_proj_h[NNODE * COUT];      // 12.8 MB (fp16)
__device__ float4 g_scores_src[NNODE];
__device__ float4 g_scores_trg[NNODE];
__device__ int    g_count[NNODE];
__device__ int    g_offsets[NNODE + 1];
__device__ int    g_blocksum[NSCAN_BLKS];
__device__ int    g_blockcarry[NSCAN_BLKS];
__device__ int    g_edge_rank[NEDGE];
__device__ int    g_sorted_si[NEDGE];
__device__ float  g_Vt[FIN * NH];

// ---------------- kernels ----------------

__global__ void zero_kernel() {
    int i = blockIdx.x * blockDim.x + threadIdx.x;
    int stride = gridDim.x * blockDim.x;
    for (int k = i; k < NNODE; k += stride) g_count[k] = 0;
}

// Vt[f,h] = sum_j Wt[f, h*32+j] * a_trg[h, j]
__global__ void fold_kernel(const float* __restrict__ Wt,
                            const float* __restrict__ a_trg) {
    int f = threadIdx.x;
    #pragma unroll
    for (int h = 0; h < NH; h++) {
        float s = 0.0f;
        #pragma unroll
        for (int j = 0; j < 32; j++)
            s += Wt[f * COUT + h * 32 + j] * a_trg[h * 32 + j];
        g_Vt[f * NH + h] = s;
    }
}

// scores_trg = trg @ Vt   (warp per node)
__global__ void strg_kernel(const float* __restrict__ trg) {
    __shared__ float Vsh[FIN * NH];
    for (int i = threadIdx.x; i < FIN * NH; i += blockDim.x) Vsh[i] = g_Vt[i];
    __syncthreads();

    int gwarp = (blockIdx.x * blockDim.x + threadIdx.x) >> 5;
    int lane = threadIdx.x & 31;
    if (gwarp >= NNODE) return;

    float4 xv = ((const float4*)(trg + (size_t)gwarp * FIN))[lane];
    int f0 = lane * 4;
    float a0, a1, a2, a3;
    a0 = xv.x * Vsh[(f0+0)*4+0] + xv.y * Vsh[(f0+1)*4+0] + xv.z * Vsh[(f0+2)*4+0] + xv.w * Vsh[(f0+3)*4+0];
    a1 = xv.x * Vsh[(f0+0)*4+1] + xv.y * Vsh[(f0+1)*4+1] + xv.z * Vsh[(f0+2)*4+1] + xv.w * Vsh[(f0+3)*4+1];
    a2 = xv.x * Vsh[(f0+0)*4+2] + xv.y * Vsh[(f0+1)*4+2] + xv.z * Vsh[(f0+2)*4+2] + xv.w * Vsh[(f0+3)*4+2];
    a3 = xv.x * Vsh[(f0+0)*4+3] + xv.y * Vsh[(f0+1)*4+3] + xv.z * Vsh[(f0+2)*4+3] + xv.w * Vsh[(f0+3)*4+3];
    #pragma unroll
    for (int o = 16; o > 0; o >>= 1) {
        a0 += __shfl_xor_sync(0xffffffffu, a0, o);
        a1 += __shfl_xor_sync(0xffffffffu, a1, o);
        a2 += __shfl_xor_sync(0xffffffffu, a2, o);
        a3 += __shfl_xor_sync(0xffffffffu, a3, o);
    }
    if (lane == 0) g_scores_trg[gwarp] = make_float4(a0, a1, a2, a3);
}

// src_proj = src @ Ws (register-blocked), fused scores_src epilogue, fp16 out.
__global__ void proj_kernel(const float* __restrict__ src,
                            const float* __restrict__ Ws,
                            const float* __restrict__ a_src) {
    extern __shared__ float sh[];
    float* Wsh = sh;                        // 128*128
    float* ash = Wsh + FIN * COUT;          // 128
    float* xsh = ash + COUT;                // PROJ_WARPS * NPW * FIN

    {
        const float4* w4 = (const float4*)Ws;
        float4* s4 = (float4*)Wsh;
        for (int i = threadIdx.x; i < FIN * COUT / 4; i += blockDim.x) s4[i] = w4[i];
        for (int i = threadIdx.x; i < COUT; i += blockDim.x) ash[i] = a_src[i];
    }
    __syncthreads();

    int lane = threadIdx.x & 31;
    int w = threadIdx.x >> 5;
    float* myx = xsh + w * (NPW * FIN);

    const int ngroups = NNODE / NPW;         // 6250 (exact)
    int group = blockIdx.x * PROJ_WARPS + w;
    int gstride = gridDim.x * PROJ_WARPS;

    for (int g = group; g < ngroups; g += gstride) {
        int n0 = g * NPW;
        #pragma unroll
        for (int r = 0; r < NPW; r++) {
            float4 xv = ((const float4*)(src + (size_t)(n0 + r) * FIN))[lane];
            ((float4*)(myx + r * FIN))[lane] = xv;
        }
        __syncwarp();

        float acc[NPW][4];
        #pragma unroll
        for (int r = 0; r < NPW; r++) { acc[r][0]=0.f; acc[r][1]=0.f; acc[r][2]=0.f; acc[r][3]=0.f; }

        #pragma unroll 4
        for (int f = 0; f < FIN; f++) {
            float4 wv = ((const float4*)(Wsh + f * COUT))[lane];
            #pragma unroll
            for (int r = 0; r < NPW; r++) {
                float xf = myx[r * FIN + f];
                acc[r][0] += xf * wv.x;
                acc[r][1] += xf * wv.y;
                acc[r][2] += xf * wv.z;
                acc[r][3] += xf * wv.w;
            }
        }

        int h = lane >> 3;
        int fi = (lane & 7) * 4;
        float c0 = ash[h * 32 + fi + 0];
        float c1 = ash[h * 32 + fi + 1];
        float c2 = ash[h * 32 + fi + 2];
        float c3 = ash[h * 32 + fi + 3];

        #pragma unroll
        for (int r = 0; r < NPW; r++) {
            int n = n0 + r;
            __half2 lo = __floats2half2_rn(acc[r][0], acc[r][1]);
            __half2 hi = __floats2half2_rn(acc[r][2], acc[r][3]);
            uint2 pk;
            pk.x = *(unsigned int*)&lo;
            pk.y = *(unsigned int*)&hi;
            ((uint2*)(g_src_proj_h + (size_t)n * COUT))[lane] = pk;

            float p = acc[r][0]*c0 + acc[r][1]*c1 + acc[r][2]*c2 + acc[r][3]*c3;
            p += __shfl_xor_sync(0xffffffffu, p, 4);
            p += __shfl_xor_sync(0xffffffffu, p, 2);
            p += __shfl_xor_sync(0xffffffffu, p, 1);
            if ((lane & 7) == 0) ((float*)g_scores_src)[n * 4 + h] = p;
        }
        __syncwarp();
    }
}

// pass 1: degree counts + ranks only (reads targets only)
__global__ void edge1_kernel(const int* __restrict__ ei) {
    int e = blockIdx.x * blockDim.x + threadIdx.x;
    if (e >= NEDGE) return;
    int ti = ei[NEDGE + e];
    g_edge_rank[e] = atomicAdd(&g_count[ti], 1);
}

// two-level scan
__global__ void scanA_kernel() {
    __shared__ int sh[SCAN_BLK];
    int tid = threadIdx.x;
    int gi = blockIdx.x * SCAN_BLK + tid;
    int v = (gi < NNODE) ? g_count[gi] : 0;
    sh[tid] = v;
    __syncthreads();
    #pragma unroll
    for (int off = 1; off < SCAN_BLK; off <<= 1) {
        int t = (tid >= off) ? sh[tid - off] : 0;
        __syncthreads();
        sh[tid] += t;
        __syncthreads();
    }
    if (gi < NNODE) g_offsets[gi + 1] = sh[tid];
    if (tid == SCAN_BLK - 1) g_blocksum[blockIdx.x] = sh[tid];
}

// one-warp shfl scan over the 49 block sums (2 elements per lane)
__global__ void scanB_kernel() {
    int lane = threadIdx.x;
    int v0 = (lane < NSCAN_BLKS) ? g_blocksum[lane] : 0;
    int v1 = (32 + lane < NSCAN_BLKS) ? g_blocksum[32 + lane] : 0;
    int i0 = v0, i1 = v1;
    #pragma unroll
    for (int o = 1; o < 32; o <<= 1) {
        int t0 = __shfl_up_sync(0xffffffffu, i0, o);
        int t1 = __shfl_up_sync(0xffffffffu, i1, o);
        if (lane >= o) { i0 += t0; i1 += t1; }
    }
    int total0 = __shfl_sync(0xffffffffu, i0, 31);
    if (lane < NSCAN_BLKS) g_blockcarry[lane] = i0 - v0;
    if (32 + lane < NSCAN_BLKS) g_blockcarry[32 + lane] = total0 + i1 - v1;
    if (lane == 0) g_offsets[0] = 0;
}

__global__ void scanC_kernel() {
    int tid = threadIdx.x;
    int gi = blockIdx.x * SCAN_BLK + tid;
    if (blockIdx.x == 0) return;
    if (gi < NNODE) g_offsets[gi + 1] += g_blockcarry[blockIdx.x];
}

// pass 2: permute source ids into CSR order (4 B payload per edge)
__global__ void edge2_kernel(const int* __restrict__ ei) {
    int e = blockIdx.x * blockDim.x + threadIdx.x;
    if (e >= NEDGE) return;
    int si = ei[e];
    int ti = ei[NEDGE + e];
    int pos = g_offsets[ti] + g_edge_rank[e];
    g_sorted_si[pos] = si;
}

// aggregation: warp per target node. Recomputes exp from scores (L2-hot
// broadcast reads), gathers fp16 src_proj rows, per-lane denominators.
// Masked 4-wide unroll: no serial remainder tail.
__global__ void agg_kernel(float* __restrict__ out) {
    int gwarp = (blockIdx.x * blockDim.x + threadIdx.x) >> 5;
    int lane = threadIdx.x & 31;
    if (gwarp >= NNODE) return;

    int s = g_offsets[gwarp];
    int e2 = g_offsets[gwarp + 1];

    const __half2* hsp = (const __half2*)g_src_proj_h;
    bool lowHalf = (lane < 16);

    float4 st = g_scores_trg[gwarp];
    float stA = lowHalf ? st.x : st.y;
    float stB = lowHalf ? st.z : st.w;

    float2 accA = make_float2(0.f, 0.f);
    float2 accB = make_float2(0.f, 0.f);
    float dA = 0.f, dB = 0.f;

    for (int i = s; i < e2; i += 4) {
        bool m1 = (i + 1 < e2), m2 = (i + 2 < e2), m3 = (i + 3 < e2);
        int si0 = g_sorted_si[i];
        int si1 = m1 ? g_sorted_si[i+1] : si0;
        int si2 = m2 ? g_sorted_si[i+2] : si0;
        int si3 = m3 ? g_sorted_si[i+3] : si0;
        float4 ss0 = g_scores_src[si0];
        float4 ss1 = g_scores_src[si1];
        float4 ss2 = g_scores_src[si2];
        float4 ss3 = g_scores_src[si3];
        __half2 vA0 = hsp[(size_t)si0*64 + lane];
        __half2 vB0 = hsp[(size_t)si0*64 + 32 + lane];
        __half2 vA1 = hsp[(size_t)si1*64 + lane];
        __half2 vB1 = hsp[(size_t)si1*64 + 32 + lane];
        __half2 vA2 = hsp[(size_t)si2*64 + lane];
        __half2 vB2 = hsp[(size_t)si2*64 + 32 + lane];
        __half2 vA3 = hsp[(size_t)si3*64 + lane];
        __half2 vB3 = hsp[(size_t)si3*64 + 32 + lane];

        float sA0 = (lowHalf ? ss0.x : ss0.y) + stA;
        float sB0 = (lowHalf ? ss0.z : ss0.w) + stB;
        float sA1 = (lowHalf ? ss1.x : ss1.y) + stA;
        float sB1 = (lowHalf ? ss1.z : ss1.w) + stB;
        float sA2 = (lowHalf ? ss2.x : ss2.y) + stA;
        float sB2 = (lowHalf ? ss2.z : ss2.w) + stB;
        float sA3 = (lowHalf ? ss3.x : ss3.y) + stA;
        float sB3 = (lowHalf ? ss3.z : ss3.w) + stB;
        float wA0 = __expf(fmaxf(sA0, 0.2f * sA0));
        float wB0 = __expf(fmaxf(sB0, 0.2f * sB0));
        float wA1 = m1 ? __expf(fmaxf(sA1, 0.2f * sA1)) : 0.f;
        float wB1 = m1 ? __expf(fmaxf(sB1, 0.2f * sB1)) : 0.f;
        float wA2 = m2 ? __expf(fmaxf(sA2, 0.2f * sA2)) : 0.f;
        float wB2 = m2 ? __expf(fmaxf(sB2, 0.2f * sB2)) : 0.f;
        float wA3 = m3 ? __expf(fmaxf(sA3, 0.2f * sA3)) : 0.f;
        float wB3 = m3 ? __expf(fmaxf(sB3, 0.2f * sB3)) : 0.f;

        float2 f;
        f = __half22float2(vA0); accA.x += wA0*f.x; accA.y += wA0*f.y;
        f = __half22float2(vB0); accB.x += wB0*f.x; accB.y += wB0*f.y;
        f = __half22float2(vA1); accA.x += wA1*f.x; accA.y += wA1*f.y;
        f = __half22float2(vB1); accB.x += wB1*f.x; accB.y += wB1*f.y;
        f = __half22float2(vA2); accA.x += wA2*f.x; accA.y += wA2*f.y;
        f = __half22float2(vB2); accB.x += wB2*f.x; accB.y += wB2*f.y;
        f = __half22float2(vA3); accA.x += wA3*f.x; accA.y += wA3*f.y;
        f = __half22float2(vB3); accB.x += wB3*f.x; accB.y += wB3*f.y;

        dA += wA0 + wA1 + wA2 + wA3;
        dB += wB0 + wB1 + wB2 + wB3;
    }

    float rA = 1.0f / (dA + 1e-16f);
    float rB = 1.0f / (dB + 1e-16f);

    float2* o = (float2*)(out + (size_t)gwarp * COUT);
    o[lane]      = make_float2(accA.x * rA, accA.y * rA);
    o[32 + lane] = make_float2(accB.x * rB, accB.y * rB);
}

// ---------------- launch ----------------

extern "C" void kernel_launch(void* const* d_in, const int* in_sizes, int n_in,
                              void* d_out, int out_size) {
    const float* trg   = (const float*)d_in[0];
    const float* src   = (const float*)d_in[1];
    const int*   ei    = (const int*)d_in[2];
    const float* Wt    = (const float*)d_in[3];
    const float* Ws    = (const float*)d_in[4];
    const float* a_src = (const float*)d_in[5];
    const float* a_trg = (const float*)d_in[6];
    float* out = (float*)d_out;

    // one-time stream/event setup (resource init only; captured work is
    // identical on every call)
    static cudaStream_t s1 = nullptr;
    static cudaEvent_t evFork = nullptr, evJoin = nullptr;
    if (s1 == nullptr) {
        cudaStreamCreateWithFlags(&s1, cudaStreamNonBlocking);
        cudaEventCreateWithFlags(&evFork, cudaEventDisableTiming);
        cudaEventCreateWithFlags(&evJoin, cudaEventDisableTiming);
    }

    const int PROJ_BLOCK = PROJ_WARPS * 32;  // 256
    size_t proj_smem = (size_t)(FIN * COUT + COUT + PROJ_WARPS * NPW * FIN) * sizeof(float);
    cudaFuncSetAttribute(proj_kernel, cudaFuncAttributeMaxDynamicSharedMemorySize,
                         (int)proj_smem);

    // preludes on default stream
    zero_kernel<<<64, 256>>>();
    fold_kernel<<<1, 128>>>(Wt, a_trg);

    // fork: CSR-build chain on s1 (depends only on ei + zeroed counts)
    cudaEventRecord(evFork, 0);
    cudaStreamWaitEvent(s1, evFork, 0);

    {
        int blocks = (NEDGE + 255) / 256;
        edge1_kernel<<<blocks, 256, 0, s1>>>(ei);
    }
    scanA_kernel<<<NSCAN_BLKS, SCAN_BLK, 0, s1>>>();
    scanB_kernel<<<1, 32, 0, s1>>>();
    scanC_kernel<<<NSCAN_BLKS, SCAN_BLK, 0, s1>>>();
    {
        int blocks = (NEDGE + 255) / 256;
        edge2_kernel<<<blocks, 256, 0, s1>>>(ei);
    }
    cudaEventRecord(evJoin, s1);

    // dense chain on default stream (runs concurrently with s1)
    {
        int blocks = (NNODE * 32 + 255) / 256;
        strg_kernel<<<blocks, 256>>>(trg);
    }
    proj_kernel<<<296, PROJ_BLOCK, proj_smem>>>(src, Ws, a_src);

    // join + aggregate
    cudaStreamWaitEvent(0, evJoin, 0);
    {
        int blocks = (NNODE * 32 + 255) / 256;
        agg_kernel<<<blocks, 256>>>(out);
    }
}

// round 8
// speedup vs baseline: 1.2571x; 1.0002x over previous
#include <cuda_runtime.h>
#include <cuda_fp16.h>
#include <math.h>

// Problem constants
#define NNODE 50000
#define NEDGE 800000
#define FIN 128
#define COUT 128   // NH*FOUT
#define NH 4

#define PROJ_WARPS 8
#define NPW 8            // nodes per warp per iteration
#define SCAN_BLK 1024
#define NSCAN_BLKS ((NNODE + SCAN_BLK - 1) / SCAN_BLK)   // 49

// ---------------- device scratch (no allocations allowed) ----------------
__device__ __half g_src_proj_h[NNODE * COUT];      // 12.8 MB (fp16)
__device__ float4 g_scores_src[NNODE];
__device__ float4 g_scores_trg[NNODE];
__device__ int    g_count[NNODE];
__device__ int    g_offsets[NNODE + 1];
__device__ int    g_blocksum[NSCAN_BLKS];
__device__ int    g_blockcarry[NSCAN_BLKS];
__device__ int    g_edge_rank[NEDGE];
__device__ int    g_sorted_si[NEDGE];
__device__ float  g_Vt[FIN * NH];

// ---------------- kernels ----------------

__global__ void zero_kernel() {
    int i = blockIdx.x * blockDim.x + threadIdx.x;
    int stride = gridDim.x * blockDim.x;
    for (int k = i; k < NNODE; k += stride) g_count[k] = 0;
}

// Vt[f,h] = sum_j Wt[f, h*32+j] * a_trg[h, j]
__global__ void fold_kernel(const float* __restrict__ Wt,
                            const float* __restrict__ a_trg) {
    int f = threadIdx.x;
    #pragma unroll
    for (int h = 0; h < NH; h++) {
        float s = 0.0f;
        #pragma unroll
        for (int j = 0; j < 32; j++)
            s += Wt[f * COUT + h * 32 + j] * a_trg[h * 32 + j];
        g_Vt[f * NH + h] = s;
    }
}

// scores_trg = trg @ Vt   (warp per node)
__global__ void strg_kernel(const float* __restrict__ trg) {
    __shared__ float Vsh[FIN * NH];
    for (int i = threadIdx.x; i < FIN * NH; i += blockDim.x) Vsh[i] = g_Vt[i];
    __syncthreads();

    int gwarp = (blockIdx.x * blockDim.x + threadIdx.x) >> 5;
    int lane = threadIdx.x & 31;
    if (gwarp >= NNODE) return;

    float4 xv = ((const float4*)(trg + (size_t)gwarp * FIN))[lane];
    int f0 = lane * 4;
    float a0, a1, a2, a3;
    a0 = xv.x * Vsh[(f0+0)*4+0] + xv.y * Vsh[(f0+1)*4+0] + xv.z * Vsh[(f0+2)*4+0] + xv.w * Vsh[(f0+3)*4+0];
    a1 = xv.x * Vsh[(f0+0)*4+1] + xv.y * Vsh[(f0+1)*4+1] + xv.z * Vsh[(f0+2)*4+1] + xv.w * Vsh[(f0+3)*4+1];
    a2 = xv.x * Vsh[(f0+0)*4+2] + xv.y * Vsh[(f0+1)*4+2] + xv.z * Vsh[(f0+2)*4+2] + xv.w * Vsh[(f0+3)*4+2];
    a3 = xv.x * Vsh[(f0+0)*4+3] + xv.y * Vsh[(f0+1)*4+3] + xv.z * Vsh[(f0+2)*4+3] + xv.w * Vsh[(f0+3)*4+3];
    #pragma unroll
    for (int o = 16; o > 0; o >>= 1) {
        a0 += __shfl_xor_sync(0xffffffffu, a0, o);
        a1 += __shfl_xor_sync(0xffffffffu, a1, o);
        a2 += __shfl_xor_sync(0xffffffffu, a2, o);
        a3 += __shfl_xor_sync(0xffffffffu, a3, o);
    }
    if (lane == 0) g_scores_trg[gwarp] = make_float4(a0, a1, a2, a3);
}

// src_proj = src @ Ws (register-blocked), fused scores_src epilogue, fp16 out.
__global__ void proj_kernel(const float* __restrict__ src,
                            const float* __restrict__ Ws,
                            const float* __restrict__ a_src) {
    extern __shared__ float sh[];
    float* Wsh = sh;                        // 128*128
    float* ash = Wsh + FIN * COUT;          // 128
    float* xsh = ash + COUT;                // PROJ_WARPS * NPW * FIN

    {
        const float4* w4 = (const float4*)Ws;
        float4* s4 = (float4*)Wsh;
        for (int i = threadIdx.x; i < FIN * COUT / 4; i += blockDim.x) s4[i] = w4[i];
        for (int i = threadIdx.x; i < COUT; i += blockDim.x) ash[i] = a_src[i];
    }
    __syncthreads();

    int lane = threadIdx.x & 31;
    int w = threadIdx.x >> 5;
    float* myx = xsh + w * (NPW * FIN);

    const int ngroups = NNODE / NPW;         // 6250 (exact)
    int group = blockIdx.x * PROJ_WARPS + w;
    int gstride = gridDim.x * PROJ_WARPS;

    for (int g = group; g < ngroups; g += gstride) {
        int n0 = g * NPW;
        #pragma unroll
        for (int r = 0; r < NPW; r++) {
            float4 xv = ((const float4*)(src + (size_t)(n0 + r) * FIN))[lane];
            ((float4*)(myx + r * FIN))[lane] = xv;
        }
        __syncwarp();

        float acc[NPW][4];
        #pragma unroll
        for (int r = 0; r < NPW; r++) { acc[r][0]=0.f; acc[r][1]=0.f; acc[r][2]=0.f; acc[r][3]=0.f; }

        #pragma unroll 4
        for (int f = 0; f < FIN; f++) {
            float4 wv = ((const float4*)(Wsh + f * COUT))[lane];
            #pragma unroll
            for (int r = 0; r < NPW; r++) {
                float xf = myx[r * FIN + f];
                acc[r][0] += xf * wv.x;
                acc[r][1] += xf * wv.y;
                acc[r][2] += xf * wv.z;
                acc[r][3] += xf * wv.w;
            }
        }

        int h = lane >> 3;
        int fi = (lane & 7) * 4;
        float c0 = ash[h * 32 + fi + 0];
        float c1 = ash[h * 32 + fi + 1];
        float c2 = ash[h * 32 + fi + 2];
        float c3 = ash[h * 32 + fi + 3];

        #pragma unroll
        for (int r = 0; r < NPW; r++) {
            int n = n0 + r;
            __half2 lo = __floats2half2_rn(acc[r][0], acc[r][1]);
            __half2 hi = __floats2half2_rn(acc[r][2], acc[r][3]);
            uint2 pk;
            pk.x = *(unsigned int*)&lo;
            pk.y = *(unsigned int*)&hi;
            ((uint2*)(g_src_proj_h + (size_t)n * COUT))[lane] = pk;

            float p = acc[r][0]*c0 + acc[r][1]*c1 + acc[r][2]*c2 + acc[r][3]*c3;
            p += __shfl_xor_sync(0xffffffffu, p, 4);
            p += __shfl_xor_sync(0xffffffffu, p, 2);
            p += __shfl_xor_sync(0xffffffffu, p, 1);
            if ((lane & 7) == 0) ((float*)g_scores_src)[n * 4 + h] = p;
        }
        __syncwarp();
    }
}

// pass 1: degree counts + ranks only (reads targets only)
__global__ void edge1_kernel(const int* __restrict__ ei) {
    int e = blockIdx.x * blockDim.x + threadIdx.x;
    if (e >= NEDGE) return;
    int ti = ei[NEDGE + e];
    g_edge_rank[e] = atomicAdd(&g_count[ti], 1);
}

// two-level scan
__global__ void scanA_kernel() {
    __shared__ int sh[SCAN_BLK];
    int tid = threadIdx.x;
    int gi = blockIdx.x * SCAN_BLK + tid;
    int v = (gi < NNODE) ? g_count[gi] : 0;
    sh[tid] = v;
    __syncthreads();
    #pragma unroll
    for (int off = 1; off < SCAN_BLK; off <<= 1) {
        int t = (tid >= off) ? sh[tid - off] : 0;
        __syncthreads();
        sh[tid] += t;
        __syncthreads();
    }
    if (gi < NNODE) g_offsets[gi + 1] = sh[tid];
    if (tid == SCAN_BLK - 1) g_blocksum[blockIdx.x] = sh[tid];
}

// one-warp shfl scan over the 49 block sums (2 elements per lane)
__global__ void scanB_kernel() {
    int lane = threadIdx.x;
    int v0 = (lane < NSCAN_BLKS) ? g_blocksum[lane] : 0;
    int v1 = (32 + lane < NSCAN_BLKS) ? g_blocksum[32 + lane] : 0;
    int i0 = v0, i1 = v1;
    #pragma unroll
    for (int o = 1; o < 32; o <<= 1) {
        int t0 = __shfl_up_sync(0xffffffffu, i0, o);
        int t1 = __shfl_up_sync(0xffffffffu, i1, o);
        if (lane >= o) { i0 += t0; i1 += t1; }
    }
    int total0 = __shfl_sync(0xffffffffu, i0, 31);
    if (lane < NSCAN_BLKS) g_blockcarry[lane] = i0 - v0;
    if (32 + lane < NSCAN_BLKS) g_blockcarry[32 + lane] = total0 + i1 - v1;
    if (lane == 0) g_offsets[0] = 0;
}

__global__ void scanC_kernel() {
    int tid = threadIdx.x;
    int gi = blockIdx.x * SCAN_BLK + tid;
    if (blockIdx.x == 0) return;
    if (gi < NNODE) g_offsets[gi + 1] += g_blockcarry[blockIdx.x];
}

// pass 2: permute source ids into CSR order (4 B payload per edge)
__global__ void edge2_kernel(const int* __restrict__ ei) {
    int e = blockIdx.x * blockDim.x + threadIdx.x;
    if (e >= NEDGE) return;
    int si = ei[e];
    int ti = ei[NEDGE + e];
    int pos = g_offsets[ti] + g_edge_rank[e];
    g_sorted_si[pos] = si;
}

// aggregation: warp per target node. Recomputes exp from scores (L2-hot
// broadcast reads), gathers fp16 src_proj rows, per-lane denominators.
// Masked 8-wide unroll for deep MLP; no serial remainder tail.
__global__ void agg_kernel(float* __restrict__ out) {
    int gwarp = (blockIdx.x * blockDim.x + threadIdx.x) >> 5;
    int lane = threadIdx.x & 31;
    if (gwarp >= NNODE) return;

    int s = g_offsets[gwarp];
    int e2 = g_offsets[gwarp + 1];

    const __half2* hsp = (const __half2*)g_src_proj_h;
    bool lowHalf = (lane < 16);

    float4 st = g_scores_trg[gwarp];
    float stA = lowHalf ? st.x : st.y;
    float stB = lowHalf ? st.z : st.w;

    float2 accA = make_float2(0.f, 0.f);
    float2 accB = make_float2(0.f, 0.f);
    float dA = 0.f, dB = 0.f;

    for (int i = s; i < e2; i += 8) {
        int sidx[8];
        bool m[8];
        #pragma unroll
        for (int q = 0; q < 8; q++) {
            m[q] = (i + q < e2);
            sidx[q] = m[q] ? g_sorted_si[i + q] : g_sorted_si[i];
        }
        float4 ss[8];
        __half2 vA[8], vB[8];
        #pragma unroll
        for (int q = 0; q < 8; q++) {
            ss[q] = g_scores_src[sidx[q]];
            vA[q] = hsp[(size_t)sidx[q] * 64 + lane];
            vB[q] = hsp[(size_t)sidx[q] * 64 + 32 + lane];
        }
        #pragma unroll
        for (int q = 0; q < 8; q++) {
            float sA = (lowHalf ? ss[q].x : ss[q].y) + stA;
            float sB = (lowHalf ? ss[q].z : ss[q].w) + stB;
            float wA = m[q] ? __expf(fmaxf(sA, 0.2f * sA)) : 0.f;
            float wB = m[q] ? __expf(fmaxf(sB, 0.2f * sB)) : 0.f;
            float2 f;
            f = __half22float2(vA[q]); accA.x += wA * f.x; accA.y += wA * f.y;
            f = __half22float2(vB[q]); accB.x += wB * f.x; accB.y += wB * f.y;
            dA += wA; dB += wB;
        }
    }

    float rA = 1.0f / (dA + 1e-16f);
    float rB = 1.0f / (dB + 1e-16f);

    float2* o = (float2*)(out + (size_t)gwarp * COUT);
    o[lane]      = make_float2(accA.x * rA, accA.y * rA);
    o[32 + lane] = make_float2(accB.x * rB, accB.y * rB);
}

// ---------------- launch ----------------

extern "C" void kernel_launch(void* const* d_in, const int* in_sizes, int n_in,
                              void* d_out, int out_size) {
    const float* trg   = (const float*)d_in[0];
    const float* src   = (const float*)d_in[1];
    const int*   ei    = (const int*)d_in[2];
    const float* Wt    = (const float*)d_in[3];
    const float* Ws    = (const float*)d_in[4];
    const float* a_src = (const float*)d_in[5];
    const float* a_trg = (const float*)d_in[6];
    float* out = (float*)d_out;

    // one-time stream/event setup (resource init only; captured work is
    // identical on every call)
    static cudaStream_t s1 = nullptr, s2 = nullptr;
    static cudaEvent_t evFork = nullptr, evJoin1 = nullptr, evJoin2 = nullptr;
    if (s1 == nullptr) {
        cudaStreamCreateWithFlags(&s1, cudaStreamNonBlocking);
        cudaStreamCreateWithFlags(&s2, cudaStreamNonBlocking);
        cudaEventCreateWithFlags(&evFork, cudaEventDisableTiming);
        cudaEventCreateWithFlags(&evJoin1, cudaEventDisableTiming);
        cudaEventCreateWithFlags(&evJoin2, cudaEventDisableTiming);
    }

    const int PROJ_BLOCK = PROJ_WARPS * 32;  // 256
    size_t proj_smem = (size_t)(FIN * COUT + COUT + PROJ_WARPS * NPW * FIN) * sizeof(float);
    cudaFuncSetAttribute(proj_kernel, cudaFuncAttributeMaxDynamicSharedMemorySize,
                         (int)proj_smem);

    // fork point (stream 0 has no prior work this call; event ties s1/s2
    // into the captured graph)
    cudaEventRecord(evFork, 0);
    cudaStreamWaitEvent(s1, evFork, 0);
    cudaStreamWaitEvent(s2, evFork, 0);

    // branch 1 (s1): CSR build — depends only on ei
    zero_kernel<<<64, 256, 0, s1>>>();
    {
        int blocks = (NEDGE + 255) / 256;
        edge1_kernel<<<blocks, 256, 0, s1>>>(ei);
    }
    scanA_kernel<<<NSCAN_BLKS, SCAN_BLK, 0, s1>>>();
    scanB_kernel<<<1, 32, 0, s1>>>();
    scanC_kernel<<<NSCAN_BLKS, SCAN_BLK, 0, s1>>>();
    {
        int blocks = (NEDGE + 255) / 256;
        edge2_kernel<<<blocks, 256, 0, s1>>>(ei);
    }
    cudaEventRecord(evJoin1, s1);

    // branch 2 (s2): fold -> strg
    fold_kernel<<<1, 128, 0, s2>>>(Wt, a_trg);
    {
        int blocks = (NNODE * 32 + 255) / 256;
        strg_kernel<<<blocks, 256, 0, s2>>>(trg);
    }
    cudaEventRecord(evJoin2, s2);

    // branch 0 (default): proj — longest pole, starts immediately
    proj_kernel<<<296, PROJ_BLOCK, proj_smem>>>(src, Ws, a_src);

    // join all -> aggregate
    cudaStreamWaitEvent(0, evJoin1, 0);
    cudaStreamWaitEvent(0, evJoin2, 0);
    {
        int blocks = (NNODE * 32 + 255) / 256;
        agg_kernel<<<blocks, 256>>>(out);
    }
}

// round 10
// speedup vs baseline: 1.3633x; 1.0845x over previous
#include <cuda_runtime.h>
#include <cuda_fp16.h>
#include <cuda_bf16.h>
#include <math.h>
#include <stdint.h>

// Problem constants
#define NNODE 50000
#define NEDGE 800000
#define FIN 128
#define COUT 128   // NH*FOUT
#define NH 4

#define SCAN_BLK 1024
#define NSCAN_BLKS ((NNODE + SCAN_BLK - 1) / SCAN_BLK)   // 49

#define TILE_M 128
#define NTILES ((NNODE + TILE_M - 1) / TILE_M)           // 391
#define LDB 136   // bf16 elems per B row: 272 B (16-aligned)
#define LDE 132   // f32 elems per epilogue row (8B-aligned ops only)

// ---------------- device scratch (no allocations allowed) ----------------
__device__ __half g_src_proj_h[NNODE * COUT];      // 12.8 MB (fp16)
__device__ float4 g_scores_src[NNODE];
__device__ float4 g_scores_trg[NNODE];
__device__ int    g_count[NNODE];
__device__ int    g_offsets[NNODE + 1];
__device__ int    g_blocksum[NSCAN_BLKS];
__device__ int    g_blockcarry[NSCAN_BLKS];
__device__ int    g_edge_rank[NEDGE];
__device__ int    g_sorted_si[NEDGE];
__device__ float  g_Vt[FIN * NH];
// Ws^T split-bf16, k-permuted into mma-fragment-pair order: [n][perm(k)]
__device__ __align__(16) __nv_bfloat16 g_BhiT[COUT * FIN];
__device__ __align__(16) __nv_bfloat16 g_BloT[COUT * FIN];

// ---------------- small kernels ----------------

__global__ void zero_kernel() {
    int i = blockIdx.x * blockDim.x + threadIdx.x;
    int stride = gridDim.x * blockDim.x;
    for (int k = i; k < NNODE; k += stride) g_count[k] = 0;
}

// Vt[f,h] = sum_j Wt[f, h*32+j] * a_trg[h, j]
__global__ void fold_kernel(const float* __restrict__ Wt,
                            const float* __restrict__ a_trg) {
    int f = threadIdx.x;
    #pragma unroll
    for (int h = 0; h < NH; h++) {
        float s = 0.0f;
        #pragma unroll
        for (int j = 0; j < 32; j++)
            s += Wt[f * COUT + h * 32 + j] * a_trg[h * 32 + j];
        g_Vt[f * NH + h] = s;
    }
}

// B = Ws^T split bf16 (hi/lo), k-index permuted so one LDS.64 yields a full
// m16n8k16 B fragment (b0 = k{c,c+1}, b1 = k{c+8,c+9}):
//   perm(k): kt=k>>4, r=k&15 -> kt*16 + ((r&7)>>1)*4 + (r>>3)*2 + (r&1)
__global__ void prepB_kernel(const float* __restrict__ Ws) {
    int t = blockIdx.x * blockDim.x + threadIdx.x;
    if (t >= FIN * COUT) return;
    int n = t >> 7;           // output col (B row)
    int k = t & 127;          // input feature
    float x = Ws[k * COUT + n];
    __nv_bfloat16 hi = __float2bfloat16(x);
    __nv_bfloat16 lo = __float2bfloat16(x - __bfloat162float(hi));
    int kt = k >> 4, r = k & 15;
    int pk = kt * 16 + ((r & 7) >> 1) * 4 + (r >> 3) * 2 + (r & 1);
    g_BhiT[n * FIN + pk] = hi;
    g_BloT[n * FIN + pk] = lo;
}

// scores_trg = trg @ Vt   (warp per node)
__global__ void strg_kernel(const float* __restrict__ trg) {
    __shared__ float Vsh[FIN * NH];
    for (int i = threadIdx.x; i < FIN * NH; i += blockDim.x) Vsh[i] = g_Vt[i];
    __syncthreads();

    int gwarp = (blockIdx.x * blockDim.x + threadIdx.x) >> 5;
    int lane = threadIdx.x & 31;
    if (gwarp >= NNODE) return;

    float4 xv = ((const float4*)(trg + (size_t)gwarp * FIN))[lane];
    int f0 = lane * 4;
    float a0, a1, a2, a3;
    a0 = xv.x * Vsh[(f0+0)*4+0] + xv.y * Vsh[(f0+1)*4+0] + xv.z * Vsh[(f0+2)*4+0] + xv.w * Vsh[(f0+3)*4+0];
    a1 = xv.x * Vsh[(f0+0)*4+1] + xv.y * Vsh[(f0+1)*4+1] + xv.z * Vsh[(f0+2)*4+1] + xv.w * Vsh[(f0+3)*4+1];
    a2 = xv.x * Vsh[(f0+0)*4+2] + xv.y * Vsh[(f0+1)*4+2] + xv.z * Vsh[(f0+2)*4+2] + xv.w * Vsh[(f0+3)*4+2];
    a3 = xv.x * Vsh[(f0+0)*4+3] + xv.y * Vsh[(f0+1)*4+3] + xv.z * Vsh[(f0+2)*4+3] + xv.w * Vsh[(f0+3)*4+3];
    #pragma unroll
    for (int o = 16; o > 0; o >>= 1) {
        a0 += __shfl_xor_sync(0xffffffffu, a0, o);
        a1 += __shfl_xor_sync(0xffffffffu, a1, o);
        a2 += __shfl_xor_sync(0xffffffffu, a2, o);
        a3 += __shfl_xor_sync(0xffffffffu, a3, o);
    }
    if (lane == 0) g_scores_trg[gwarp] = make_float4(a0, a1, a2, a3);
}

// ---------------- mma.sync split-bf16 projection ----------------

__device__ __forceinline__ void mma16816(float* c, const uint32_t* a,
                                         uint32_t b0, uint32_t b1) {
    asm volatile(
        "mma.sync.aligned.m16n8k16.row.col.f32.bf16.bf16.f32 "
        "{%0,%1,%2,%3}, {%4,%5,%6,%7}, {%8,%9}, {%0,%1,%2,%3};"
        : "+f"(c[0]), "+f"(c[1]), "+f"(c[2]), "+f"(c[3])
        : "r"(a[0]), "r"(a[1]), "r"(a[2]), "r"(a[3]), "r"(b0), "r"(b1));
}

__device__ __forceinline__ void split2(float2 v, uint32_t& hi, uint32_t& lo) {
    __nv_bfloat162 h = __floats2bfloat162_rn(v.x, v.y);
    float hx = __bfloat162float(__low2bfloat16(h));
    float hy = __bfloat162float(__high2bfloat16(h));
    __nv_bfloat162 l = __floats2bfloat162_rn(v.x - hx, v.y - hy);
    hi = *(uint32_t*)&h;
    lo = *(uint32_t*)&l;
}

// smem: [0, 34816) sBhi, [34816, 69632) sBlo; epilogue overlays [0, 67584);
// ash at 69632 (512 B). Total 70144 B. All B rows 272 B (16-aligned).
#define SM_BHI 0
#define SM_BLO 34816
#define SM_ASH 69632
#define PROJ_SMEM (SM_ASH + 512)

__global__ void __launch_bounds__(256)
proj_mma_kernel(const float* __restrict__ src,
                const float* __restrict__ a_src) {
    extern __shared__ char smem[];
    __nv_bfloat16* sBhi = (__nv_bfloat16*)(smem + SM_BHI);
    __nv_bfloat16* sBlo = (__nv_bfloat16*)(smem + SM_BLO);
    float* ash = (float*)(smem + SM_ASH);

    int tid = threadIdx.x;
    int w = tid >> 5;
    int lane = tid & 31;
    int n0 = blockIdx.x * TILE_M;

    // copy pre-split permuted B rows (128 bf16 each) into padded smem
    {
        const uint4* bh = (const uint4*)g_BhiT;   // 16 uint4 per row
        const uint4* bl = (const uint4*)g_BloT;
        for (int i = tid; i < COUT * 16; i += 256) {
            int n = i >> 4, kk = (i & 15) * 8;
            *(uint4*)(sBhi + n * LDB + kk) = bh[i];
            *(uint4*)(sBlo + n * LDB + kk) = bl[i];
        }
        for (int i = tid; i < COUT; i += 256) ash[i] = a_src[i];
    }
    __syncthreads();

    int gID = lane >> 2;        // 0..7
    int tig = lane & 3;         // 0..3
    int m0 = n0 + w * 16 + gID;
    int m1 = m0 + 8;
    bool v0 = m0 < NNODE, v1 = m1 < NNODE;
    const float* row0 = src + (size_t)m0 * FIN;
    const float* row1 = src + (size_t)m1 * FIN;

    float acc[16][4];
    #pragma unroll
    for (int nt = 0; nt < 16; nt++) {
        acc[nt][0] = 0.f; acc[nt][1] = 0.f; acc[nt][2] = 0.f; acc[nt][3] = 0.f;
    }

    #pragma unroll
    for (int kt = 0; kt < 8; kt++) {
        int k0 = kt * 16 + tig * 2;
        float2 z = make_float2(0.f, 0.f);
        float2 L0 = v0 ? *(const float2*)(row0 + k0) : z;
        float2 L1 = v1 ? *(const float2*)(row1 + k0) : z;
        float2 L2 = v0 ? *(const float2*)(row0 + k0 + 8) : z;
        float2 L3 = v1 ? *(const float2*)(row1 + k0 + 8) : z;

        uint32_t ahi[4], alo[4];
        split2(L0, ahi[0], alo[0]);
        split2(L1, ahi[1], alo[1]);
        split2(L2, ahi[2], alo[2]);
        split2(L3, ahi[3], alo[3]);

        int kb = kt * 16 + tig * 4;
        #pragma unroll
        for (int nt = 0; nt < 16; nt++) {
            int n = nt * 8 + gID;
            uint2 bh = *(const uint2*)(sBhi + n * LDB + kb);
            uint2 bl = *(const uint2*)(sBlo + n * LDB + kb);
            mma16816(acc[nt], ahi, bh.x, bh.y);
            mma16816(acc[nt], ahi, bl.x, bl.y);
            mma16816(acc[nt], alo, bh.x, bh.y);
        }
    }

    // epilogue: stage warp's 16x128 f32 strip over the B region
    __syncthreads();
    float* epi = (float*)(smem + w * (16 * LDE * 4));
    #pragma unroll
    for (int nt = 0; nt < 16; nt++) {
        int cb = nt * 8 + tig * 2;
        *(float2*)(epi + gID * LDE + cb)       = make_float2(acc[nt][0], acc[nt][1]);
        *(float2*)(epi + (gID + 8) * LDE + cb) = make_float2(acc[nt][2], acc[nt][3]);
    }
    __syncwarp();

    {
        int row = lane >> 1;      // 0..15
        int half = lane & 1;      // cols half*64 .. +63
        int m = n0 + w * 16 + row;
        if (m < NNODE) {
            const float* v = epi + row * LDE + half * 64;
            float p0 = 0.f, p1 = 0.f;
            #pragma unroll
            for (int j = 0; j < 32; j++) {
                p0 += v[j]      * ash[half * 64 + j];
                p1 += v[32 + j] * ash[half * 64 + 32 + j];
            }
            ((float2*)&g_scores_src[m])[half] = make_float2(p0, p1);

            uint32_t pk[16], pk2[16];
            #pragma unroll
            for (int j = 0; j < 16; j++) {
                __half2 h = __floats2half2_rn(v[2*j], v[2*j+1]);
                pk[j] = *(uint32_t*)&h;
            }
            #pragma unroll
            for (int j = 0; j < 16; j++) {
                __half2 h = __floats2half2_rn(v[32 + 2*j], v[32 + 2*j+1]);
                pk2[j] = *(uint32_t*)&h;
            }
            uint4* dst = (uint4*)(g_src_proj_h + (size_t)m * COUT + half * 64);
            #pragma unroll
            for (int q = 0; q < 4; q++)
                dst[q] = make_uint4(pk[q*4], pk[q*4+1], pk[q*4+2], pk[q*4+3]);
            #pragma unroll
            for (int q = 0; q < 4; q++)
                dst[4 + q] = make_uint4(pk2[q*4], pk2[q*4+1], pk2[q*4+2], pk2[q*4+3]);
        }
    }
}

// ---------------- edge pipeline ----------------

__global__ void edge1_kernel(const int* __restrict__ ei) {
    int e = blockIdx.x * blockDim.x + threadIdx.x;
    if (e >= NEDGE) return;
    int ti = ei[NEDGE + e];
    g_edge_rank[e] = atomicAdd(&g_count[ti], 1);
}

__global__ void scanA_kernel() {
    __shared__ int sh[SCAN_BLK];
    int tid = threadIdx.x;
    int gi = blockIdx.x * SCAN_BLK + tid;
    int v = (gi < NNODE) ? g_count[gi] : 0;
    sh[tid] = v;
    __syncthreads();
    #pragma unroll
    for (int off = 1; off < SCAN_BLK; off <<= 1) {
        int t = (tid >= off) ? sh[tid - off] : 0;
        __syncthreads();
        sh[tid] += t;
        __syncthreads();
    }
    if (gi < NNODE) g_offsets[gi + 1] = sh[tid];
    if (tid == SCAN_BLK - 1) g_blocksum[blockIdx.x] = sh[tid];
}

__global__ void scanB_kernel() {
    int lane = threadIdx.x;
    int v0 = (lane < NSCAN_BLKS) ? g_blocksum[lane] : 0;
    int v1 = (32 + lane < NSCAN_BLKS) ? g_blocksum[32 + lane] : 0;
    int i0 = v0, i1 = v1;
    #pragma unroll
    for (int o = 1; o < 32; o <<= 1) {
        int t0 = __shfl_up_sync(0xffffffffu, i0, o);
        int t1 = __shfl_up_sync(0xffffffffu, i1, o);
        if (lane >= o) { i0 += t0; i1 += t1; }
    }
    int total0 = __shfl_sync(0xffffffffu, i0, 31);
    if (lane < NSCAN_BLKS) g_blockcarry[lane] = i0 - v0;
    if (32 + lane < NSCAN_BLKS) g_blockcarry[32 + lane] = total0 + i1 - v1;
    if (lane == 0) g_offsets[0] = 0;
}

__global__ void scanC_kernel() {
    int tid = threadIdx.x;
    int gi = blockIdx.x * SCAN_BLK + tid;
    if (blockIdx.x == 0) return;
    if (gi < NNODE) g_offsets[gi + 1] += g_blockcarry[blockIdx.x];
}

__global__ void edge2_kernel(const int* __restrict__ ei) {
    int e = blockIdx.x * blockDim.x + threadIdx.x;
    if (e >= NEDGE) return;
    int si = ei[e];
    int ti = ei[NEDGE + e];
    int pos = g_offsets[ti] + g_edge_rank[e];
    g_sorted_si[pos] = si;
}

// aggregation: warp per target node; masked 8-wide unroll; per-lane denoms.
__global__ void agg_kernel(float* __restrict__ out) {
    int gwarp = (blockIdx.x * blockDim.x + threadIdx.x) >> 5;
    int lane = threadIdx.x & 31;
    if (gwarp >= NNODE) return;

    int s = g_offsets[gwarp];
    int e2 = g_offsets[gwarp + 1];

    const __half2* hsp = (const __half2*)g_src_proj_h;
    bool lowHalf = (lane < 16);

    float4 st = g_scores_trg[gwarp];
    float stA = lowHalf ? st.x : st.y;
    float stB = lowHalf ? st.z : st.w;

    float2 accA = make_float2(0.f, 0.f);
    float2 accB = make_float2(0.f, 0.f);
    float dA = 0.f, dB = 0.f;

    for (int i = s; i < e2; i += 8) {
        int sidx[8];
        bool m[8];
        #pragma unroll
        for (int q = 0; q < 8; q++) {
            m[q] = (i + q < e2);
            sidx[q] = m[q] ? g_sorted_si[i + q] : g_sorted_si[i];
        }
        float4 ss[8];
        __half2 vA[8], vB[8];
        #pragma unroll
        for (int q = 0; q < 8; q++) {
            ss[q] = g_scores_src[sidx[q]];
            vA[q] = hsp[(size_t)sidx[q] * 64 + lane];
            vB[q] = hsp[(size_t)sidx[q] * 64 + 32 + lane];
        }
        #pragma unroll
        for (int q = 0; q < 8; q++) {
            float sA = (lowHalf ? ss[q].x : ss[q].y) + stA;
            float sB = (lowHalf ? ss[q].z : ss[q].w) + stB;
            float wA = m[q] ? __expf(fmaxf(sA, 0.2f * sA)) : 0.f;
            float wB = m[q] ? __expf(fmaxf(sB, 0.2f * sB)) : 0.f;
            float2 f;
            f = __half22float2(vA[q]); accA.x += wA * f.x; accA.y += wA * f.y;
            f = __half22float2(vB[q]); accB.x += wB * f.x; accB.y += wB * f.y;
            dA += wA; dB += wB;
        }
    }

    float rA = 1.0f / (dA + 1e-16f);
    float rB = 1.0f / (dB + 1e-16f);

    float2* o = (float2*)(out + (size_t)gwarp * COUT);
    o[lane]      = make_float2(accA.x * rA, accA.y * rA);
    o[32 + lane] = make_float2(accB.x * rB, accB.y * rB);
}

// ---------------- launch ----------------

extern "C" void kernel_launch(void* const* d_in, const int* in_sizes, int n_in,
                              void* d_out, int out_size) {
    const float* trg   = (const float*)d_in[0];
    const float* src   = (const float*)d_in[1];
    const int*   ei    = (const int*)d_in[2];
    const float* Wt    = (const float*)d_in[3];
    const float* Ws    = (const float*)d_in[4];
    const float* a_src = (const float*)d_in[5];
    const float* a_trg = (const float*)d_in[6];
    float* out = (float*)d_out;

    static cudaStream_t s1 = nullptr, s2 = nullptr;
    static cudaEvent_t evFork = nullptr, evJoin1 = nullptr, evJoin2 = nullptr;
    if (s1 == nullptr) {
        cudaStreamCreateWithFlags(&s1, cudaStreamNonBlocking);
        cudaStreamCreateWithFlags(&s2, cudaStreamNonBlocking);
        cudaEventCreateWithFlags(&evFork, cudaEventDisableTiming);
        cudaEventCreateWithFlags(&evJoin1, cudaEventDisableTiming);
        cudaEventCreateWithFlags(&evJoin2, cudaEventDisableTiming);
    }

    cudaFuncSetAttribute(proj_mma_kernel,
                         cudaFuncAttributeMaxDynamicSharedMemorySize, PROJ_SMEM);

    // fork
    cudaEventRecord(evFork, 0);
    cudaStreamWaitEvent(s1, evFork, 0);
    cudaStreamWaitEvent(s2, evFork, 0);

    // branch 1 (s1): CSR build — depends only on ei
    zero_kernel<<<64, 256, 0, s1>>>();
    {
        int blocks = (NEDGE + 255) / 256;
        edge1_kernel<<<blocks, 256, 0, s1>>>(ei);
    }
    scanA_kernel<<<NSCAN_BLKS, SCAN_BLK, 0, s1>>>();
    scanB_kernel<<<1, 32, 0, s1>>>();
    scanC_kernel<<<NSCAN_BLKS, SCAN_BLK, 0, s1>>>();
    {
        int blocks = (NEDGE + 255) / 256;
        edge2_kernel<<<blocks, 256, 0, s1>>>(ei);
    }
    cudaEventRecord(evJoin1, s1);

    // branch 2 (s2): fold -> strg
    fold_kernel<<<1, 128, 0, s2>>>(Wt, a_trg);
    {
        int blocks = (NNODE * 32 + 255) / 256;
        strg_kernel<<<blocks, 256, 0, s2>>>(trg);
    }
    cudaEventRecord(evJoin2, s2);

    // branch 0 (default): prepB -> tensor proj
    prepB_kernel<<<64, 256>>>(Ws);
    proj_mma_kernel<<<NTILES, 256, PROJ_SMEM>>>(src, a_src);

    // join all -> aggregate
    cudaStreamWaitEvent(0, evJoin1, 0);
    cudaStreamWaitEvent(0, evJoin2, 0);
    {
        int blocks = (NNODE * 32 + 255) / 256;
        agg_kernel<<<blocks, 256>>>(out);
    }
}